// round 2
// baseline (speedup 1.0000x reference)
#include <cuda_runtime.h>
#include <cstdint>
#include <cstddef>

#define DEV __device__ __forceinline__

constexpr int kA = 8;
constexpr int kD = 128;
constexpr int kH = 64;
constexpr int kG = 192;   // 3*H
constexpr int kQ = 16;
constexpr int BB = 128;   // batch rows per CTA
constexpr int NTHREADS = 512;

// ---- shared memory layout (in floats) ----
// Strides chosen ≡ 4 (mod 32) so row-strided accesses hit distinct banks.
constexpr int XS_STRIDE = 132;                  // X tile [BB][132]  (lives in [0, 16896))
constexpr int ZS = 68;                          // stride for z1 / h / hnew tiles
constexpr int OFF_Z1  = 0;                      // z1   [BB][68]  (after X is dead)
constexpr int OFF_HN  = BB * ZS;                // 8704  hnew [BB][68]
constexpr int OFF_W   = 2 * BB * ZS;            // 17408 weights region
constexpr int WST     = 196;                    // stride of transposed gate weights
constexpr int OFF_WHH = OFF_W + kH * WST;       // 29952
constexpr int OFF_H   = OFF_W + 2 * kH * WST;   // 42496 h_in [BB][68]
constexpr int OFF_B   = OFF_H + BB * ZS;        // 51200 biases
constexpr int OFF_B1  = OFF_B;                  // 64
constexpr int OFF_BIH = OFF_B + 64;             // 192
constexpr int OFF_BHH = OFF_B + 256;            // 192
constexpr int OFF_B2  = OFF_B + 448;            // 16
constexpr int SMEM_FLOATS = OFF_B + 464;        // 51664 floats = 206656 B

// ---- packed f32x2 helpers (ptxas will NOT auto-fuse; must be inline PTX) ----
DEV unsigned long long fma2(unsigned long long a, unsigned long long b,
                            unsigned long long c) {
  unsigned long long d;
  asm("fma.rn.f32x2 %0, %1, %2, %3;" : "=l"(d) : "l"(a), "l"(b), "l"(c));
  return d;
}
DEV unsigned long long dup2(float x) {
  unsigned long long r;
  asm("mov.b64 %0, {%1, %1};" : "=l"(r) : "f"(x));
  return r;
}
DEV void upk2(unsigned long long v, float& x, float& y) {
  asm("mov.b64 {%0, %1}, %2;" : "=f"(x), "=f"(y) : "l"(v));
}

DEV float sigmoidf_(float x) {
  float e = __expf(-x);
  return __fdividef(1.0f, 1.0f + e);
}
DEV float tanhf_(float x) {
  float e = __expf(2.0f * x);
  return 1.0f - __fdividef(2.0f, e + 1.0f);
}

__global__ void __launch_bounds__(NTHREADS, 1)
rnn_fused_kernel(const float* __restrict__ inputs,
                 const float* __restrict__ hidden,
                 const float* __restrict__ W1,  const float* __restrict__ b1,
                 const float* __restrict__ Wih, const float* __restrict__ bih,
                 const float* __restrict__ Whh, const float* __restrict__ bhh,
                 const float* __restrict__ W2,  const float* __restrict__ b2,
                 float* __restrict__ out_q, float* __restrict__ out_h)
{
  extern __shared__ float smf[];
  const int a  = blockIdx.y;
  const int b0 = blockIdx.x * BB;
  const int tid = threadIdx.x;
  const int tx = tid & 15;          // 16 column-groups of 4 -> 64 cols
  const int ty = tid >> 4;          // 32 row-groups of 4   -> 128 rows
  const int r0 = ty * 4;
  const int c0 = tx * 4;

  // ============ cooperative loads: X, W1^T, H_in, biases ============
  {
    const float* xg = inputs + ((size_t)b0 * kA + a) * kD;
    #pragma unroll 4
    for (int idx = tid; idx < BB * (kD / 4); idx += NTHREADS) {
      int row = idx >> 5, c4 = (idx & 31) << 2;
      float4 v = *reinterpret_cast<const float4*>(xg + (size_t)row * (kA * kD) + c4);
      *reinterpret_cast<float4*>(&smf[row * XS_STRIDE + c4]) = v;
    }
    const float* w1g = W1 + (size_t)a * kH * kD;
    #pragma unroll 4
    for (int idx = tid; idx < kH * kD; idx += NTHREADS) {
      int h = idx >> 7, d = idx & 127;
      smf[OFF_W + d * ZS + h] = w1g[idx];          // W1t[d][h], stride 68
    }
    const float* hg = hidden + ((size_t)b0 * kA + a) * kH;
    #pragma unroll 4
    for (int idx = tid; idx < BB * (kH / 4); idx += NTHREADS) {
      int row = idx >> 4, c4 = (idx & 15) << 2;
      float4 v = *reinterpret_cast<const float4*>(hg + (size_t)row * (kA * kH) + c4);
      *reinterpret_cast<float4*>(&smf[OFF_H + row * ZS + c4]) = v;
    }
    if (tid < 64)        smf[OFF_B1  + tid      ] = b1 [a * kH + tid];
    else if (tid < 256)  smf[OFF_BIH + tid -  64] = bih[a * kG + tid -  64];
    else if (tid < 448)  smf[OFF_BHH + tid - 256] = bhh[a * kG + tid - 256];
    else if (tid < 464)  smf[OFF_B2  + tid - 448] = b2 [a * kQ + tid - 448];
  }
  __syncthreads();

  // ============ stage 1: z1 = relu(X @ W1^T + b1) ============
  unsigned long long z1acc[4][2];
  #pragma unroll
  for (int i = 0; i < 4; ++i) { z1acc[i][0] = 0ull; z1acc[i][1] = 0ull; }

  #pragma unroll 2
  for (int k4 = 0; k4 < kD / 4; ++k4) {
    float4 xr[4];
    #pragma unroll
    for (int i = 0; i < 4; ++i)
      xr[i] = *reinterpret_cast<const float4*>(&smf[(r0 + i) * XS_STRIDE + k4 * 4]);
    #pragma unroll
    for (int kk = 0; kk < 4; ++kk) {
      const float* wrow = &smf[OFF_W + (k4 * 4 + kk) * ZS + c0];
      unsigned long long w01 = *reinterpret_cast<const unsigned long long*>(wrow);
      unsigned long long w23 = *reinterpret_cast<const unsigned long long*>(wrow + 2);
      #pragma unroll
      for (int i = 0; i < 4; ++i) {
        float xv = reinterpret_cast<const float*>(&xr[i])[kk];
        unsigned long long xx = dup2(xv);
        z1acc[i][0] = fma2(w01, xx, z1acc[i][0]);
        z1acc[i][1] = fma2(w23, xx, z1acc[i][1]);
      }
    }
  }
  __syncthreads();   // all X / W1t reads done; regions may be reused now

  {
    float bx = smf[OFF_B1 + c0 + 0], by = smf[OFF_B1 + c0 + 1];
    float bz = smf[OFF_B1 + c0 + 2], bw = smf[OFF_B1 + c0 + 3];
    #pragma unroll
    for (int i = 0; i < 4; ++i) {
      float v0, v1, v2, v3;
      upk2(z1acc[i][0], v0, v1);
      upk2(z1acc[i][1], v2, v3);
      float4 z;
      z.x = fmaxf(v0 + bx, 0.f); z.y = fmaxf(v1 + by, 0.f);
      z.z = fmaxf(v2 + bz, 0.f); z.w = fmaxf(v3 + bw, 0.f);
      *reinterpret_cast<float4*>(&smf[OFF_Z1 + (r0 + i) * ZS + c0]) = z;
    }
  }

  // load gate weights transposed: Wih_t[k][g], Whh_t[k][g] (stride 196)
  {
    const float* wg  = Wih + (size_t)a * kG * kH;
    const float* wg2 = Whh + (size_t)a * kG * kH;
    #pragma unroll 4
    for (int idx = tid; idx < kG * kH; idx += NTHREADS) {
      int g = idx >> 6, k = idx & 63;
      smf[OFF_W   + k * WST + g] = wg [idx];
      smf[OFF_WHH + k * WST + g] = wg2[idx];
    }
  }
  __syncthreads();

  // ============ stage 2: gate GEMMs ============
  unsigned long long ar[4][2], az[4][2], an[4][2], ah[4][2];
  #pragma unroll
  for (int i = 0; i < 4; ++i) {
    ar[i][0] = ar[i][1] = 0ull;
    az[i][0] = az[i][1] = 0ull;
    an[i][0] = an[i][1] = 0ull;
    ah[i][0] = ah[i][1] = 0ull;
  }

  #pragma unroll 2
  for (int k2 = 0; k2 < kH / 2; ++k2) {
    const int k = k2 * 2;
    float2 zf[4], hf[4];
    #pragma unroll
    for (int i = 0; i < 4; ++i) {
      zf[i] = *reinterpret_cast<const float2*>(&smf[OFF_Z1 + (r0 + i) * ZS + k]);
      hf[i] = *reinterpret_cast<const float2*>(&smf[OFF_H  + (r0 + i) * ZS + k]);
    }
    #pragma unroll
    for (int kk = 0; kk < 2; ++kk) {
      const float* wi = &smf[OFF_W   + (k + kk) * WST];
      const float* wh = &smf[OFF_WHH + (k + kk) * WST];
      unsigned long long wri0 = *reinterpret_cast<const unsigned long long*>(wi + c0);
      unsigned long long wri1 = *reinterpret_cast<const unsigned long long*>(wi + c0 + 2);
      unsigned long long wzi0 = *reinterpret_cast<const unsigned long long*>(wi + 64 + c0);
      unsigned long long wzi1 = *reinterpret_cast<const unsigned long long*>(wi + 64 + c0 + 2);
      unsigned long long wni0 = *reinterpret_cast<const unsigned long long*>(wi + 128 + c0);
      unsigned long long wni1 = *reinterpret_cast<const unsigned long long*>(wi + 128 + c0 + 2);
      unsigned long long wrh0 = *reinterpret_cast<const unsigned long long*>(wh + c0);
      unsigned long long wrh1 = *reinterpret_cast<const unsigned long long*>(wh + c0 + 2);
      unsigned long long wzh0 = *reinterpret_cast<const unsigned long long*>(wh + 64 + c0);
      unsigned long long wzh1 = *reinterpret_cast<const unsigned long long*>(wh + 64 + c0 + 2);
      unsigned long long wnh0 = *reinterpret_cast<const unsigned long long*>(wh + 128 + c0);
      unsigned long long wnh1 = *reinterpret_cast<const unsigned long long*>(wh + 128 + c0 + 2);
      #pragma unroll
      for (int i = 0; i < 4; ++i) {
        float zv = kk ? zf[i].y : zf[i].x;
        float hv = kk ? hf[i].y : hf[i].x;
        unsigned long long zz = dup2(zv);
        unsigned long long hh = dup2(hv);
        ar[i][0] = fma2(wri0, zz, ar[i][0]); ar[i][0] = fma2(wrh0, hh, ar[i][0]);
        ar[i][1] = fma2(wri1, zz, ar[i][1]); ar[i][1] = fma2(wrh1, hh, ar[i][1]);
        az[i][0] = fma2(wzi0, zz, az[i][0]); az[i][0] = fma2(wzh0, hh, az[i][0]);
        az[i][1] = fma2(wzi1, zz, az[i][1]); az[i][1] = fma2(wzh1, hh, az[i][1]);
        an[i][0] = fma2(wni0, zz, an[i][0]);
        an[i][1] = fma2(wni1, zz, an[i][1]);
        ah[i][0] = fma2(wnh0, hh, ah[i][0]);
        ah[i][1] = fma2(wnh1, hh, ah[i][1]);
      }
    }
  }

  // ============ stage 3: GRU gates + h_new ============
  {
    float bir[4], biz[4], bin[4], bhr[4], bhz[4], bhn[4];
    #pragma unroll
    for (int j = 0; j < 4; ++j) {
      bir[j] = smf[OFF_BIH +       c0 + j];
      biz[j] = smf[OFF_BIH +  64 + c0 + j];
      bin[j] = smf[OFF_BIH + 128 + c0 + j];
      bhr[j] = smf[OFF_BHH +       c0 + j];
      bhz[j] = smf[OFF_BHH +  64 + c0 + j];
      bhn[j] = smf[OFF_BHH + 128 + c0 + j];
    }
    #pragma unroll
    for (int i = 0; i < 4; ++i) {
      float arf[4], azf[4], anf[4], ahf[4];
      upk2(ar[i][0], arf[0], arf[1]); upk2(ar[i][1], arf[2], arf[3]);
      upk2(az[i][0], azf[0], azf[1]); upk2(az[i][1], azf[2], azf[3]);
      upk2(an[i][0], anf[0], anf[1]); upk2(an[i][1], anf[2], anf[3]);
      upk2(ah[i][0], ahf[0], ahf[1]); upk2(ah[i][1], ahf[2], ahf[3]);
      const float4 hold = *reinterpret_cast<const float4*>(&smf[OFF_H + (r0 + i) * ZS + c0]);
      const float ho[4] = {hold.x, hold.y, hold.z, hold.w};
      float hn[4];
      #pragma unroll
      for (int j = 0; j < 4; ++j) {
        float R  = sigmoidf_(arf[j] + bir[j] + bhr[j]);
        float Zg = sigmoidf_(azf[j] + biz[j] + bhz[j]);
        float n  = tanhf_(anf[j] + bin[j] + R * (ahf[j] + bhn[j]));
        hn[j] = n + Zg * (ho[j] - n);          // (1-z)*n + z*h
      }
      float4 hv4 = make_float4(hn[0], hn[1], hn[2], hn[3]);
      *reinterpret_cast<float4*>(&smf[OFF_HN + (r0 + i) * ZS + c0]) = hv4;
      *reinterpret_cast<float4*>(&out_h[((size_t)(b0 + r0 + i) * kA + a) * kH + c0]) = hv4;
    }
  }
  __syncthreads();   // stage-2 weight reads done; HN tile complete

  // ============ stage 4: q = h_new @ W2^T + b2 ============
  {
    const float* w2g = W2 + (size_t)a * kQ * kH;
    for (int idx = tid; idx < kQ * kH; idx += NTHREADS) {
      int n = idx >> 6, k = idx & 63;
      smf[OFF_W + k * kQ + n] = w2g[idx];      // W2t[k][n]
    }
  }
  __syncthreads();
  {
    const int qc  = tid & 15;
    const int qr0 = (tid >> 4) * 4;
    float qa0 = 0.f, qa1 = 0.f, qa2 = 0.f, qa3 = 0.f;
    #pragma unroll 8
    for (int k = 0; k < kH; ++k) {
      float w = smf[OFF_W + k * kQ + qc];
      qa0 = fmaf(smf[OFF_HN + (qr0 + 0) * ZS + k], w, qa0);
      qa1 = fmaf(smf[OFF_HN + (qr0 + 1) * ZS + k], w, qa1);
      qa2 = fmaf(smf[OFF_HN + (qr0 + 2) * ZS + k], w, qa2);
      qa3 = fmaf(smf[OFF_HN + (qr0 + 3) * ZS + k], w, qa3);
    }
    float bq = smf[OFF_B2 + qc];
    out_q[((size_t)(b0 + qr0 + 0) * kA + a) * kQ + qc] = qa0 + bq;
    out_q[((size_t)(b0 + qr0 + 1) * kA + a) * kQ + qc] = qa1 + bq;
    out_q[((size_t)(b0 + qr0 + 2) * kA + a) * kQ + qc] = qa2 + bq;
    out_q[((size_t)(b0 + qr0 + 3) * kA + a) * kQ + qc] = qa3 + bq;
  }
}

extern "C" void kernel_launch(void* const* d_in, const int* in_sizes, int n_in,
                              void* d_out, int out_size) {
  (void)n_in; (void)out_size;
  const float* inputs = (const float*)d_in[0];
  const float* hidden = (const float*)d_in[1];
  const float* W1  = (const float*)d_in[2];
  const float* b1  = (const float*)d_in[3];
  const float* Wih = (const float*)d_in[4];
  const float* bih = (const float*)d_in[5];
  const float* Whh = (const float*)d_in[6];
  const float* bhh = (const float*)d_in[7];
  const float* W2  = (const float*)d_in[8];
  const float* b2  = (const float*)d_in[9];

  const int B = in_sizes[0] / (kA * kD);   // 16384
  float* out_q = (float*)d_out;
  float* out_h = out_q + (size_t)B * kA * kQ;

  const size_t smem = (size_t)SMEM_FLOATS * sizeof(float);  // 206656 B
  cudaFuncSetAttribute(rnn_fused_kernel,
                       cudaFuncAttributeMaxDynamicSharedMemorySize, (int)smem);
  dim3 grid(B / BB, kA, 1);
  rnn_fused_kernel<<<grid, NTHREADS, smem>>>(inputs, hidden, W1, b1, Wih, bih,
                                             Whh, bhh, W2, b2, out_q, out_h);
}

// round 4
// speedup vs baseline: 1.6454x; 1.6454x over previous
#include <cuda_runtime.h>
#include <cuda_bf16.h>
#include <cstdint>
#include <cstddef>

#define DEV __device__ __forceinline__

constexpr int NT = 256;   // 8 warps
constexpr int BB = 128;   // batch rows per CTA

// ---- smem layout in 32-bit words ----
constexpr int B1O = 0, BRO = 64, BZO = 128, BINO = 192, BHNO = 256, B2O = 320;
constexpr int RA   = 352;                 // region A: 17408 words
constexpr int XH   = RA;                  // X hi  [128][68]
constexpr int XL   = RA + 8704;           // X lo
constexpr int WIHH = RA;                  // (reuse) Wih hi [192][36]
constexpr int WIHL = RA + 6912;
constexpr int HNH  = RA;                  // (reuse) h_new hi [128][36]
constexpr int HNL  = RA + 4608;
constexpr int RB   = RA + 17408;          // region B: 9216 words
constexpr int W1Ho = RB;                  // W1 hi [64][68]
constexpr int W1Lo = RB + 4352;
constexpr int Z1H  = RB;                  // (reuse) z1 hi [128][36]
constexpr int Z1L  = RB + 4608;
constexpr int RC   = RB + 9216;           // h_in hi/lo [128][36]
constexpr int HHq  = RC;
constexpr int HLq  = RC + 4608;
constexpr int RD   = RC + 9216;           // Whh hi/lo [192][36]
constexpr int WHH_H = RD;
constexpr int WHH_L = RD + 6912;
constexpr int RE   = RD + 13824;          // W2 hi/lo [16][36]
constexpr int W2Ho = RE;
constexpr int W2Lo = RE + 576;
constexpr int SMEM_WORDS = RE + 1152;     // 51168 words = 204672 B

DEV void split2(float x, float y, uint32_t& hi, uint32_t& lo) {
  __nv_bfloat16 xh = __float2bfloat16(x), yh = __float2bfloat16(y);
  __nv_bfloat16 xl = __float2bfloat16(x - __bfloat162float(xh));
  __nv_bfloat16 yl = __float2bfloat16(y - __bfloat162float(yh));
  hi = (uint32_t)__bfloat16_as_ushort(xh) | ((uint32_t)__bfloat16_as_ushort(yh) << 16);
  lo = (uint32_t)__bfloat16_as_ushort(xl) | ((uint32_t)__bfloat16_as_ushort(yl) << 16);
}
DEV float bfbits2f(uint32_t b) { return __uint_as_float(b << 16); }
DEV float sigm(float x) { return __fdividef(1.f, 1.f + __expf(-x)); }
DEV float tanh_(float x) { float e = __expf(2.f * x); return 1.f - __fdividef(2.f, e + 1.f); }

DEV uint32_t smem_u32(const void* p) {
  uint32_t r;
  asm("{ .reg .u64 t; cvta.to.shared.u64 t, %1; cvt.u32.u64 %0, t; }" : "=r"(r) : "l"(p));
  return r;
}
DEV void mma16816(float* c, const uint32_t* a, uint32_t b0, uint32_t b1) {
  asm volatile(
      "mma.sync.aligned.m16n8k16.row.col.f32.bf16.bf16.f32 "
      "{%0,%1,%2,%3}, {%4,%5,%6,%7}, {%8,%9}, {%0,%1,%2,%3};"
      : "+f"(c[0]), "+f"(c[1]), "+f"(c[2]), "+f"(c[3])
      : "r"(a[0]), "r"(a[1]), "r"(a[2]), "r"(a[3]), "r"(b0), "r"(b1));
}
DEV void ldsm4(uint32_t* r, uint32_t addr) {
  asm volatile("ldmatrix.sync.aligned.m8n8.x4.shared.b16 {%0,%1,%2,%3}, [%4];"
               : "=r"(r[0]), "=r"(r[1]), "=r"(r[2]), "=r"(r[3]) : "r"(addr));
}
DEV void ldsm2(uint32_t& r0, uint32_t& r1, uint32_t addr) {
  asm volatile("ldmatrix.sync.aligned.m8n8.x2.shared.b16 {%0,%1}, [%2];"
               : "=r"(r0), "=r"(r1) : "r"(addr));
}

__global__ void __launch_bounds__(NT, 1)
rnn_wmma_kernel(const float* __restrict__ inputs, const float* __restrict__ hidden,
                const float* __restrict__ W1, const float* __restrict__ b1g,
                const float* __restrict__ Wih, const float* __restrict__ bihg,
                const float* __restrict__ Whh, const float* __restrict__ bhhg,
                const float* __restrict__ W2, const float* __restrict__ b2g,
                float* __restrict__ out_q, float* __restrict__ out_h)
{
  extern __shared__ uint32_t smu[];
  float* smf = (float*)smu;
  const uint32_t sb = smem_u32(smu);
  const int a = blockIdx.y;
  const int b0 = blockIdx.x * BB;
  const int tid = threadIdx.x;
  const int w = tid >> 5, lane = tid & 31;
  const int mw = w >> 1, nw = w & 1;
  const int g = lane >> 2, cq = lane & 3;
  const int l15 = lane & 15, lhalf = lane >> 4;       // A ldsm addressing
  const int l7 = lane & 7, l8b = (lane >> 3) & 1;     // B ldsm addressing

  // ================= cooperative load + fp32->bf16 hi/lo convert =================
  if (tid < 64) {
    smf[B1O + tid]  = b1g[a * 64 + tid];
    smf[BRO + tid]  = bihg[a * 192 + tid]       + bhhg[a * 192 + tid];
    smf[BZO + tid]  = bihg[a * 192 + 64 + tid]  + bhhg[a * 192 + 64 + tid];
    smf[BINO + tid] = bihg[a * 192 + 128 + tid];
    smf[BHNO + tid] = bhhg[a * 192 + 128 + tid];
  } else if (tid < 80) {
    smf[B2O + tid - 64] = b2g[a * 16 + tid - 64];
  }
  {
    const float* xg = inputs + ((size_t)b0 * 8 + a) * 128;
    #pragma unroll 4
    for (int f = tid; f < 4096; f += NT) {            // X [128][128]
      int row = f >> 5, p4 = (f & 31) * 2;
      float4 v = *(const float4*)(xg + (size_t)row * 1024 + p4 * 2);
      uint32_t h0, l0, h1, l1;
      split2(v.x, v.y, h0, l0); split2(v.z, v.w, h1, l1);
      smu[XH + row * 68 + p4] = h0; smu[XH + row * 68 + p4 + 1] = h1;
      smu[XL + row * 68 + p4] = l0; smu[XL + row * 68 + p4 + 1] = l1;
    }
    const float* w1g = W1 + (size_t)a * 64 * 128;
    #pragma unroll 4
    for (int f = tid; f < 2048; f += NT) {            // W1 [64][128]
      int n = f >> 5, p4 = (f & 31) * 2;
      float4 v = *(const float4*)(w1g + (size_t)n * 128 + p4 * 2);
      uint32_t h0, l0, h1, l1;
      split2(v.x, v.y, h0, l0); split2(v.z, v.w, h1, l1);
      smu[W1Ho + n * 68 + p4] = h0; smu[W1Ho + n * 68 + p4 + 1] = h1;
      smu[W1Lo + n * 68 + p4] = l0; smu[W1Lo + n * 68 + p4 + 1] = l1;
    }
    const float* hg = hidden + ((size_t)b0 * 8 + a) * 64;
    #pragma unroll 4
    for (int f = tid; f < 2048; f += NT) {            // h [128][64]
      int row = f >> 4, p4 = (f & 15) * 2;
      float4 v = *(const float4*)(hg + (size_t)row * 512 + p4 * 2);
      uint32_t h0, l0, h1, l1;
      split2(v.x, v.y, h0, l0); split2(v.z, v.w, h1, l1);
      smu[HHq + row * 36 + p4] = h0; smu[HHq + row * 36 + p4 + 1] = h1;
      smu[HLq + row * 36 + p4] = l0; smu[HLq + row * 36 + p4 + 1] = l1;
    }
    const float* whg = Whh + (size_t)a * 192 * 64;
    #pragma unroll 4
    for (int f = tid; f < 3072; f += NT) {            // Whh [192][64]
      int n = f >> 4, p4 = (f & 15) * 2;
      float4 v = *(const float4*)(whg + (size_t)n * 64 + p4 * 2);
      uint32_t h0, l0, h1, l1;
      split2(v.x, v.y, h0, l0); split2(v.z, v.w, h1, l1);
      smu[WHH_H + n * 36 + p4] = h0; smu[WHH_H + n * 36 + p4 + 1] = h1;
      smu[WHH_L + n * 36 + p4] = l0; smu[WHH_L + n * 36 + p4 + 1] = l1;
    }
    const float* w2g = W2 + (size_t)a * 16 * 64;
    for (int f = tid; f < 256; f += NT) {             // W2 [16][64]
      int n = f >> 4, p4 = (f & 15) * 2;
      float4 v = *(const float4*)(w2g + (size_t)n * 64 + p4 * 2);
      uint32_t h0, l0, h1, l1;
      split2(v.x, v.y, h0, l0); split2(v.z, v.w, h1, l1);
      smu[W2Ho + n * 36 + p4] = h0; smu[W2Ho + n * 36 + p4 + 1] = h1;
      smu[W2Lo + n * 36 + p4] = l0; smu[W2Lo + n * 36 + p4 + 1] = l1;
    }
  }
  __syncthreads();

  // ================= stage 1: z1 = relu(X @ W1^T + b1) =================
  float acc1[2][4][4];
  #pragma unroll
  for (int mt = 0; mt < 2; ++mt)
    #pragma unroll
    for (int nt = 0; nt < 4; ++nt)
      #pragma unroll
      for (int e = 0; e < 4; ++e) acc1[mt][nt][e] = 0.f;

  #pragma unroll
  for (int kc = 0; kc < 8; ++kc) {
    uint32_t ah[2][4], al[2][4];
    #pragma unroll
    for (int mt = 0; mt < 2; ++mt) {
      uint32_t aoff = (uint32_t)(32 * mw + 16 * mt + l15) * 68 + kc * 8 + lhalf * 4;
      ldsm4(ah[mt], sb + 4 * (XH + aoff));
      ldsm4(al[mt], sb + 4 * (XL + aoff));
    }
    #pragma unroll
    for (int nt = 0; nt < 4; ++nt) {
      uint32_t boff = (uint32_t)(32 * nw + 8 * nt + l7) * 68 + kc * 8 + l8b * 4;
      uint32_t bh0, bh1, bl0, bl1;
      ldsm2(bh0, bh1, sb + 4 * (W1Ho + boff));
      ldsm2(bl0, bl1, sb + 4 * (W1Lo + boff));
      #pragma unroll
      for (int mt = 0; mt < 2; ++mt) {
        mma16816(acc1[mt][nt], ah[mt], bh0, bh1);
        mma16816(acc1[mt][nt], al[mt], bh0, bh1);
        mma16816(acc1[mt][nt], ah[mt], bl0, bl1);
      }
    }
  }
  __syncthreads();   // W1/X regions now dead

  // epilogue 1: bias+relu, pack z1 hi/lo into region B
  #pragma unroll
  for (int mt = 0; mt < 2; ++mt)
    #pragma unroll
    for (int nt = 0; nt < 4; ++nt) {
      int col = 32 * nw + 8 * nt + 2 * cq;
      int pidx = 16 * nw + 4 * nt + cq;
      float bx = smf[B1O + col], by = smf[B1O + col + 1];
      #pragma unroll
      for (int s = 0; s < 2; ++s) {
        int row = 32 * mw + 16 * mt + g + 8 * s;
        float v0 = fmaxf(acc1[mt][nt][2 * s] + bx, 0.f);
        float v1 = fmaxf(acc1[mt][nt][2 * s + 1] + by, 0.f);
        uint32_t ph, pl;
        split2(v0, v1, ph, pl);
        smu[Z1H + row * 36 + pidx] = ph;
        smu[Z1L + row * 36 + pidx] = pl;
      }
    }
  // load Wih into region A (X dead)
  {
    const float* wig = Wih + (size_t)a * 192 * 64;
    #pragma unroll 4
    for (int f = tid; f < 3072; f += NT) {
      int n = f >> 4, p4 = (f & 15) * 2;
      float4 v = *(const float4*)(wig + (size_t)n * 64 + p4 * 2);
      uint32_t h0, l0, h1, l1;
      split2(v.x, v.y, h0, l0); split2(v.z, v.w, h1, l1);
      smu[WIHH + n * 36 + p4] = h0; smu[WIHH + n * 36 + p4 + 1] = h1;
      smu[WIHL + n * 36 + p4] = l0; smu[WIHL + n * 36 + p4 + 1] = l1;
    }
  }
  __syncthreads();

  // ================= stage 2: gate GEMMs =================
  // N-space 256: [0..63]=r, [64..127]=z (z1*Wih + h*Whh), [128..191]=i_n (z1*Wih),
  //              [192..255]=h_n (h*Whh rows 128..191). Warp takes n-tiles with parity nw.
  float acc2[2][16][4];
  #pragma unroll
  for (int mt = 0; mt < 2; ++mt)
    #pragma unroll
    for (int j = 0; j < 16; ++j)
      #pragma unroll
      for (int e = 0; e < 4; ++e) acc2[mt][j][e] = 0.f;

  #pragma unroll
  for (int kc = 0; kc < 4; ++kc) {
    uint32_t zh[2][4], zl[2][4], hh_[2][4], hl_[2][4];
    #pragma unroll
    for (int mt = 0; mt < 2; ++mt) {
      uint32_t aoff = (uint32_t)(32 * mw + 16 * mt + l15) * 36 + kc * 8 + lhalf * 4;
      ldsm4(zh[mt], sb + 4 * (Z1H + aoff));
      ldsm4(zl[mt], sb + 4 * (Z1L + aoff));
      ldsm4(hh_[mt], sb + 4 * (HHq + aoff));
      ldsm4(hl_[mt], sb + 4 * (HLq + aoff));
    }
    uint32_t bbase = (uint32_t)l7 * 36 + kc * 8 + l8b * 4;
    #pragma unroll
    for (int j = 0; j < 16; ++j) {
      int ntp = 2 * j + nw;
      if (j < 12) {                       // z1 @ Wih rows 8*ntp
        uint32_t bh0, bh1, bl0, bl1;
        uint32_t o = (uint32_t)(8 * ntp) * 36 + bbase;
        ldsm2(bh0, bh1, sb + 4 * (WIHH + o));
        ldsm2(bl0, bl1, sb + 4 * (WIHL + o));
        #pragma unroll
        for (int mt = 0; mt < 2; ++mt) {
          mma16816(acc2[mt][j], zh[mt], bh0, bh1);
          mma16816(acc2[mt][j], zl[mt], bh0, bh1);
          mma16816(acc2[mt][j], zh[mt], bl0, bl1);
        }
      }
      if (j < 8 || j >= 12) {             // h @ Whh rows 8*ntp (rz) or 8*ntp-64 (n)
        int n0 = (j < 8) ? 8 * ntp : 8 * ntp - 64;
        uint32_t bh0, bh1, bl0, bl1;
        uint32_t o = (uint32_t)n0 * 36 + bbase;
        ldsm2(bh0, bh1, sb + 4 * (WHH_H + o));
        ldsm2(bl0, bl1, sb + 4 * (WHH_L + o));
        #pragma unroll
        for (int mt = 0; mt < 2; ++mt) {
          mma16816(acc2[mt][j], hh_[mt], bh0, bh1);
          mma16816(acc2[mt][j], hl_[mt], bh0, bh1);
          mma16816(acc2[mt][j], hh_[mt], bl0, bl1);
        }
      }
    }
  }
  __syncthreads();   // Wih region dead -> reuse for h_new

  // ================= epilogue 2: GRU -> h_new =================
  #pragma unroll
  for (int mt = 0; mt < 2; ++mt)
    #pragma unroll
    for (int jr = 0; jr < 4; ++jr) {
      int ntp = 2 * jr + nw;
      int cb = 8 * ntp + 2 * cq;          // col 0..63 (even)
      int pidx = 4 * ntp + cq;
      float brv0 = smf[BRO + cb],  brv1 = smf[BRO + cb + 1];
      float bzv0 = smf[BZO + cb],  bzv1 = smf[BZO + cb + 1];
      float biv0 = smf[BINO + cb], biv1 = smf[BINO + cb + 1];
      float bnv0 = smf[BHNO + cb], bnv1 = smf[BHNO + cb + 1];
      #pragma unroll
      for (int s = 0; s < 2; ++s) {
        int row = 32 * mw + 16 * mt + g + 8 * s;
        uint32_t uh = smu[HHq + row * 36 + pidx], ul = smu[HLq + row * 36 + pidx];
        float ho0 = bfbits2f(uh & 0xffffu) + bfbits2f(ul & 0xffffu);
        float ho1 = bfbits2f(uh >> 16) + bfbits2f(ul >> 16);
        float rv0 = sigm(acc2[mt][jr][2 * s] + brv0);
        float rv1 = sigm(acc2[mt][jr][2 * s + 1] + brv1);
        float zv0 = sigm(acc2[mt][jr + 4][2 * s] + bzv0);
        float zv1 = sigm(acc2[mt][jr + 4][2 * s + 1] + bzv1);
        float nv0 = tanh_(acc2[mt][jr + 8][2 * s] + biv0 +
                          rv0 * (acc2[mt][jr + 12][2 * s] + bnv0));
        float nv1 = tanh_(acc2[mt][jr + 8][2 * s + 1] + biv1 +
                          rv1 * (acc2[mt][jr + 12][2 * s + 1] + bnv1));
        float hn0 = nv0 + zv0 * (ho0 - nv0);
        float hn1 = nv1 + zv1 * (ho1 - nv1);
        uint32_t ph, pl;
        split2(hn0, hn1, ph, pl);
        smu[HNH + row * 36 + pidx] = ph;
        smu[HNL + row * 36 + pidx] = pl;
        *(float2*)(out_h + ((size_t)(b0 + row) * 8 + a) * 64 + cb) = make_float2(hn0, hn1);
      }
    }
  __syncthreads();

  // ================= stage 3: q = h_new @ W2^T + b2 =================
  float acc3[2][4];
  #pragma unroll
  for (int mt = 0; mt < 2; ++mt)
    #pragma unroll
    for (int e = 0; e < 4; ++e) acc3[mt][e] = 0.f;

  #pragma unroll
  for (int kc = 0; kc < 4; ++kc) {
    uint32_t boff = (uint32_t)(8 * nw + l7) * 36 + kc * 8 + l8b * 4;
    uint32_t bh0, bh1, bl0, bl1;
    ldsm2(bh0, bh1, sb + 4 * (W2Ho + boff));
    ldsm2(bl0, bl1, sb + 4 * (W2Lo + boff));
    #pragma unroll
    for (int mt = 0; mt < 2; ++mt) {
      uint32_t aoff = (uint32_t)(32 * mw + 16 * mt + l15) * 36 + kc * 8 + lhalf * 4;
      uint32_t ah[4], al[4];
      ldsm4(ah, sb + 4 * (HNH + aoff));
      ldsm4(al, sb + 4 * (HNL + aoff));
      mma16816(acc3[mt], ah, bh0, bh1);
      mma16816(acc3[mt], al, bh0, bh1);
      mma16816(acc3[mt], ah, bl0, bl1);
    }
  }
  {
    int colb = 8 * nw + 2 * cq;
    float bq0 = smf[B2O + colb], bq1 = smf[B2O + colb + 1];
    #pragma unroll
    for (int mt = 0; mt < 2; ++mt)
      #pragma unroll
      for (int s = 0; s < 2; ++s) {
        int row = 32 * mw + 16 * mt + g + 8 * s;
        float q0 = acc3[mt][2 * s] + bq0;
        float q1 = acc3[mt][2 * s + 1] + bq1;
        *(float2*)(out_q + ((size_t)(b0 + row) * 8 + a) * 16 + colb) = make_float2(q0, q1);
      }
  }
}

extern "C" void kernel_launch(void* const* d_in, const int* in_sizes, int n_in,
                              void* d_out, int out_size) {
  (void)n_in; (void)out_size;
  const float* inputs = (const float*)d_in[0];
  const float* hidden = (const float*)d_in[1];
  const float* W1  = (const float*)d_in[2];
  const float* b1  = (const float*)d_in[3];
  const float* Wih = (const float*)d_in[4];
  const float* bih = (const float*)d_in[5];
  const float* Whh = (const float*)d_in[6];
  const float* bhh = (const float*)d_in[7];
  const float* W2  = (const float*)d_in[8];
  const float* b2  = (const float*)d_in[9];

  const int B = in_sizes[0] / (8 * 128);   // 16384
  float* out_q = (float*)d_out;
  float* out_h = out_q + (size_t)B * 8 * 16;

  const size_t smem = (size_t)SMEM_WORDS * 4;   // 204672 B
  cudaFuncSetAttribute(rnn_wmma_kernel,
                       cudaFuncAttributeMaxDynamicSharedMemorySize, (int)smem);
  dim3 grid(B / BB, 8, 1);
  rnn_wmma_kernel<<<grid, NT, smem>>>(inputs, hidden, W1, b1, Wih, bih,
                                      Whh, bhh, W2, b2, out_q, out_h);
}

// round 5
// speedup vs baseline: 1.7116x; 1.0402x over previous
#include <cuda_runtime.h>
#include <cuda_bf16.h>
#include <cstdint>
#include <cstddef>

#define DEV __device__ __forceinline__

constexpr int NT = 256;   // 8 warps: 4 m-warps x 2 n-warps
constexpr int BB = 64;    // batch rows per tile
constexpr int NTILE = 16; // tiles per CTA (16384 / 16 CTAs / 64 rows)

// ---- smem layout in 32-bit words ----
constexpr int B1O = 0, BRO = 64, BZO = 128, BINO = 192, BHNO = 256, B2O = 320;
constexpr int W1H = 352;              // [64][68] hi
constexpr int W1L = W1H + 4352;       // lo
constexpr int WIHH = W1L + 4352;      // [192][36]
constexpr int WIHL = WIHH + 6912;
constexpr int WHH_H = WIHL + 6912;
constexpr int WHH_L = WHH_H + 6912;
constexpr int W2H = WHH_L + 6912;     // [16][36]
constexpr int W2L = W2H + 576;
constexpr int XR  = W2L + 576;        // 9216-word region: X hi/lo, later z1 + hn
constexpr int XH  = XR;               // X hi [64][68]
constexpr int XL  = XR + 4352;        // X lo
constexpr int Z1H = XR;               // z1 hi [64][36] (X dead)
constexpr int Z1L = XR + 2304;
constexpr int HNH = XR + 4608;        // h_new hi [64][36]
constexpr int HNL = XR + 6912;
constexpr int HHq = XR + 9216;        // h_in hi [64][36]
constexpr int HLq = HHq + 2304;
constexpr int SMEM_WORDS = HLq + 2304;   // 51680 words = 206720 B

DEV void split2(float x, float y, uint32_t& hi, uint32_t& lo) {
  __nv_bfloat16 xh = __float2bfloat16(x), yh = __float2bfloat16(y);
  __nv_bfloat16 xl = __float2bfloat16(x - __bfloat162float(xh));
  __nv_bfloat16 yl = __float2bfloat16(y - __bfloat162float(yh));
  hi = (uint32_t)__bfloat16_as_ushort(xh) | ((uint32_t)__bfloat16_as_ushort(yh) << 16);
  lo = (uint32_t)__bfloat16_as_ushort(xl) | ((uint32_t)__bfloat16_as_ushort(yl) << 16);
}
DEV float bfbits2f(uint32_t b) { return __uint_as_float(b << 16); }
DEV float sigm(float x) { return __fdividef(1.f, 1.f + __expf(-x)); }
DEV float tanh_(float x) { float e = __expf(2.f * x); return 1.f - __fdividef(2.f, e + 1.f); }

DEV uint32_t smem_u32(const void* p) {
  uint32_t r;
  asm("{ .reg .u64 t; cvta.to.shared.u64 t, %1; cvt.u32.u64 %0, t; }" : "=r"(r) : "l"(p));
  return r;
}
DEV void mma16816(float* c, const uint32_t* a, uint32_t b0, uint32_t b1) {
  asm volatile(
      "mma.sync.aligned.m16n8k16.row.col.f32.bf16.bf16.f32 "
      "{%0,%1,%2,%3}, {%4,%5,%6,%7}, {%8,%9}, {%0,%1,%2,%3};"
      : "+f"(c[0]), "+f"(c[1]), "+f"(c[2]), "+f"(c[3])
      : "r"(a[0]), "r"(a[1]), "r"(a[2]), "r"(a[3]), "r"(b0), "r"(b1));
}
DEV void ldsm4(uint32_t* r, uint32_t addr) {
  asm volatile("ldmatrix.sync.aligned.m8n8.x4.shared.b16 {%0,%1,%2,%3}, [%4];"
               : "=r"(r[0]), "=r"(r[1]), "=r"(r[2]), "=r"(r[3]) : "r"(addr));
}
DEV void ldsm2(uint32_t& r0, uint32_t& r1, uint32_t addr) {
  asm volatile("ldmatrix.sync.aligned.m8n8.x2.shared.b16 {%0,%1}, [%2];"
               : "=r"(r0), "=r"(r1) : "r"(addr));
}

__global__ void __launch_bounds__(NT, 1)
rnn_persist_kernel(const float* __restrict__ inputs, const float* __restrict__ hidden,
                   const float* __restrict__ W1, const float* __restrict__ b1g,
                   const float* __restrict__ Wih, const float* __restrict__ bihg,
                   const float* __restrict__ Whh, const float* __restrict__ bhhg,
                   const float* __restrict__ W2, const float* __restrict__ b2g,
                   float* __restrict__ out_q, float* __restrict__ out_h)
{
  extern __shared__ uint32_t smu[];
  float* smf = (float*)smu;
  const uint32_t sb = smem_u32(smu);
  const int a = blockIdx.y;
  const int tid = threadIdx.x;
  const int w = tid >> 5, lane = tid & 31;
  const int mw = w >> 1, nw = w & 1;          // 4 m-warps x 2 n-warps
  const int g = lane >> 2, cq = lane & 3;
  const int l15 = lane & 15, lhalf = lane >> 4;
  const int l7 = lane & 7, l8b = (lane >> 3) & 1;

  // ================= one-time: biases + weights -> bf16 hi/lo =================
  if (tid < 64) {
    smf[B1O + tid]  = b1g[a * 64 + tid];
    smf[BRO + tid]  = bihg[a * 192 + tid]       + bhhg[a * 192 + tid];
    smf[BZO + tid]  = bihg[a * 192 + 64 + tid]  + bhhg[a * 192 + 64 + tid];
    smf[BINO + tid] = bihg[a * 192 + 128 + tid];
    smf[BHNO + tid] = bhhg[a * 192 + 128 + tid];
  } else if (tid < 80) {
    smf[B2O + tid - 64] = b2g[a * 16 + tid - 64];
  }
  {
    const float* w1g = W1 + (size_t)a * 64 * 128;
    #pragma unroll 4
    for (int f = tid; f < 2048; f += NT) {            // W1 [64][128]
      int n = f >> 5, p4 = (f & 31) * 2;
      float4 v = *(const float4*)(w1g + (size_t)n * 128 + p4 * 2);
      uint32_t h0, l0, h1, l1;
      split2(v.x, v.y, h0, l0); split2(v.z, v.w, h1, l1);
      smu[W1H + n * 68 + p4] = h0; smu[W1H + n * 68 + p4 + 1] = h1;
      smu[W1L + n * 68 + p4] = l0; smu[W1L + n * 68 + p4 + 1] = l1;
    }
    const float* wig = Wih + (size_t)a * 192 * 64;
    #pragma unroll 4
    for (int f = tid; f < 3072; f += NT) {            // Wih [192][64]
      int n = f >> 4, p4 = (f & 15) * 2;
      float4 v = *(const float4*)(wig + (size_t)n * 64 + p4 * 2);
      uint32_t h0, l0, h1, l1;
      split2(v.x, v.y, h0, l0); split2(v.z, v.w, h1, l1);
      smu[WIHH + n * 36 + p4] = h0; smu[WIHH + n * 36 + p4 + 1] = h1;
      smu[WIHL + n * 36 + p4] = l0; smu[WIHL + n * 36 + p4 + 1] = l1;
    }
    const float* whg = Whh + (size_t)a * 192 * 64;
    #pragma unroll 4
    for (int f = tid; f < 3072; f += NT) {            // Whh [192][64]
      int n = f >> 4, p4 = (f & 15) * 2;
      float4 v = *(const float4*)(whg + (size_t)n * 64 + p4 * 2);
      uint32_t h0, l0, h1, l1;
      split2(v.x, v.y, h0, l0); split2(v.z, v.w, h1, l1);
      smu[WHH_H + n * 36 + p4] = h0; smu[WHH_H + n * 36 + p4 + 1] = h1;
      smu[WHH_L + n * 36 + p4] = l0; smu[WHH_L + n * 36 + p4 + 1] = l1;
    }
    const float* w2g = W2 + (size_t)a * 16 * 64;
    for (int f = tid; f < 256; f += NT) {             // W2 [16][64]
      int n = f >> 4, p4 = (f & 15) * 2;
      float4 v = *(const float4*)(w2g + (size_t)n * 64 + p4 * 2);
      uint32_t h0, l0, h1, l1;
      split2(v.x, v.y, h0, l0); split2(v.z, v.w, h1, l1);
      smu[W2H + n * 36 + p4] = h0; smu[W2H + n * 36 + p4 + 1] = h1;
      smu[W2L + n * 36 + p4] = l0; smu[W2L + n * 36 + p4 + 1] = l1;
    }
  }
  __syncthreads();

  // ================= tile loop =================
  for (int t = 0; t < NTILE; ++t) {
    const int b0 = blockIdx.x * (NTILE * BB) + t * BB;

    // ---- load + convert X, h ----
    {
      const float* xg = inputs + ((size_t)b0 * 8 + a) * 128;
      #pragma unroll 8
      for (int f = tid; f < 2048; f += NT) {          // X [64][128]
        int row = f >> 5, p4 = (f & 31) * 2;
        float4 v = *(const float4*)(xg + (size_t)row * 1024 + p4 * 2);
        uint32_t h0, l0, h1, l1;
        split2(v.x, v.y, h0, l0); split2(v.z, v.w, h1, l1);
        smu[XH + row * 68 + p4] = h0; smu[XH + row * 68 + p4 + 1] = h1;
        smu[XL + row * 68 + p4] = l0; smu[XL + row * 68 + p4 + 1] = l1;
      }
      const float* hg = hidden + ((size_t)b0 * 8 + a) * 64;
      #pragma unroll 4
      for (int f = tid; f < 1024; f += NT) {          // h [64][64]
        int row = f >> 4, p4 = (f & 15) * 2;
        float4 v = *(const float4*)(hg + (size_t)row * 512 + p4 * 2);
        uint32_t h0, l0, h1, l1;
        split2(v.x, v.y, h0, l0); split2(v.z, v.w, h1, l1);
        smu[HHq + row * 36 + p4] = h0; smu[HHq + row * 36 + p4 + 1] = h1;
        smu[HLq + row * 36 + p4] = l0; smu[HLq + row * 36 + p4 + 1] = l1;
      }
    }
    __syncthreads();

    // ---- stage 1: z1 = relu(X @ W1^T + b1) ----
    float acc1[4][4];
    #pragma unroll
    for (int nt = 0; nt < 4; ++nt)
      #pragma unroll
      for (int e = 0; e < 4; ++e) acc1[nt][e] = 0.f;

    #pragma unroll
    for (int kc = 0; kc < 8; ++kc) {
      uint32_t ah[4], al[4];
      uint32_t aoff = (uint32_t)(16 * mw + l15) * 68 + kc * 8 + lhalf * 4;
      ldsm4(ah, sb + 4 * (XH + aoff));
      ldsm4(al, sb + 4 * (XL + aoff));
      #pragma unroll
      for (int nt = 0; nt < 4; ++nt) {
        uint32_t boff = (uint32_t)(32 * nw + 8 * nt + l7) * 68 + kc * 8 + l8b * 4;
        uint32_t bh0, bh1, bl0, bl1;
        ldsm2(bh0, bh1, sb + 4 * (W1H + boff));
        ldsm2(bl0, bl1, sb + 4 * (W1L + boff));
        mma16816(acc1[nt], ah, bh0, bh1);
        mma16816(acc1[nt], al, bh0, bh1);
        mma16816(acc1[nt], ah, bl0, bl1);
      }
    }
    __syncthreads();   // X region dead

    // ---- epilogue 1: bias+relu -> z1 hi/lo ----
    #pragma unroll
    for (int nt = 0; nt < 4; ++nt) {
      int col = 32 * nw + 8 * nt + 2 * cq;
      int pidx = 16 * nw + 4 * nt + cq;
      float bx = smf[B1O + col], by = smf[B1O + col + 1];
      #pragma unroll
      for (int s = 0; s < 2; ++s) {
        int row = 16 * mw + g + 8 * s;
        float v0 = fmaxf(acc1[nt][2 * s] + bx, 0.f);
        float v1 = fmaxf(acc1[nt][2 * s + 1] + by, 0.f);
        uint32_t ph, pl;
        split2(v0, v1, ph, pl);
        smu[Z1H + row * 36 + pidx] = ph;
        smu[Z1L + row * 36 + pidx] = pl;
      }
    }
    __syncthreads();

    // ---- stage 2: gate GEMMs (N-space 256: r | z | i_n | h_n) ----
    float acc2[16][4];
    #pragma unroll
    for (int j = 0; j < 16; ++j)
      #pragma unroll
      for (int e = 0; e < 4; ++e) acc2[j][e] = 0.f;

    #pragma unroll
    for (int kc = 0; kc < 4; ++kc) {
      uint32_t zh[4], zl[4], hh_[4], hl_[4];
      uint32_t aoff = (uint32_t)(16 * mw + l15) * 36 + kc * 8 + lhalf * 4;
      ldsm4(zh, sb + 4 * (Z1H + aoff));
      ldsm4(zl, sb + 4 * (Z1L + aoff));
      ldsm4(hh_, sb + 4 * (HHq + aoff));
      ldsm4(hl_, sb + 4 * (HLq + aoff));
      uint32_t bbase = (uint32_t)l7 * 36 + kc * 8 + l8b * 4;
      #pragma unroll
      for (int j = 0; j < 16; ++j) {
        int ntp = 2 * j + nw;
        if (j < 12) {                       // z1 @ Wih rows 8*ntp
          uint32_t bh0, bh1, bl0, bl1;
          uint32_t o = (uint32_t)(8 * ntp) * 36 + bbase;
          ldsm2(bh0, bh1, sb + 4 * (WIHH + o));
          ldsm2(bl0, bl1, sb + 4 * (WIHL + o));
          mma16816(acc2[j], zh, bh0, bh1);
          mma16816(acc2[j], zl, bh0, bh1);
          mma16816(acc2[j], zh, bl0, bl1);
        }
        if (j < 8 || j >= 12) {             // h @ Whh
          int n0 = (j < 8) ? 8 * ntp : 8 * ntp - 64;
          uint32_t bh0, bh1, bl0, bl1;
          uint32_t o = (uint32_t)n0 * 36 + bbase;
          ldsm2(bh0, bh1, sb + 4 * (WHH_H + o));
          ldsm2(bl0, bl1, sb + 4 * (WHH_L + o));
          mma16816(acc2[j], hh_, bh0, bh1);
          mma16816(acc2[j], hl_, bh0, bh1);
          mma16816(acc2[j], hh_, bl0, bl1);
        }
      }
    }
    __syncthreads();

    // ---- epilogue 2: GRU -> h_new (smem hi/lo + gmem) ----
    #pragma unroll
    for (int jr = 0; jr < 4; ++jr) {
      int ntp = 2 * jr + nw;
      int cb = 8 * ntp + 2 * cq;
      int pidx = 4 * ntp + cq;
      float brv0 = smf[BRO + cb],  brv1 = smf[BRO + cb + 1];
      float bzv0 = smf[BZO + cb],  bzv1 = smf[BZO + cb + 1];
      float biv0 = smf[BINO + cb], biv1 = smf[BINO + cb + 1];
      float bnv0 = smf[BHNO + cb], bnv1 = smf[BHNO + cb + 1];
      #pragma unroll
      for (int s = 0; s < 2; ++s) {
        int row = 16 * mw + g + 8 * s;
        uint32_t uh = smu[HHq + row * 36 + pidx], ul = smu[HLq + row * 36 + pidx];
        float ho0 = bfbits2f(uh & 0xffffu) + bfbits2f(ul & 0xffffu);
        float ho1 = bfbits2f(uh >> 16) + bfbits2f(ul >> 16);
        float rv0 = sigm(acc2[jr][2 * s] + brv0);
        float rv1 = sigm(acc2[jr][2 * s + 1] + brv1);
        float zv0 = sigm(acc2[jr + 4][2 * s] + bzv0);
        float zv1 = sigm(acc2[jr + 4][2 * s + 1] + bzv1);
        float nv0 = tanh_(acc2[jr + 8][2 * s] + biv0 +
                          rv0 * (acc2[jr + 12][2 * s] + bnv0));
        float nv1 = tanh_(acc2[jr + 8][2 * s + 1] + biv1 +
                          rv1 * (acc2[jr + 12][2 * s + 1] + bnv1));
        float hn0 = nv0 + zv0 * (ho0 - nv0);
        float hn1 = nv1 + zv1 * (ho1 - nv1);
        uint32_t ph, pl;
        split2(hn0, hn1, ph, pl);
        smu[HNH + row * 36 + pidx] = ph;
        smu[HNL + row * 36 + pidx] = pl;
        *(float2*)(out_h + ((size_t)(b0 + row) * 8 + a) * 64 + cb) = make_float2(hn0, hn1);
      }
    }
    __syncthreads();

    // ---- stage 3: q = h_new @ W2^T + b2 ----
    float acc3[4] = {0.f, 0.f, 0.f, 0.f};
    #pragma unroll
    for (int kc = 0; kc < 4; ++kc) {
      uint32_t boff = (uint32_t)(8 * nw + l7) * 36 + kc * 8 + l8b * 4;
      uint32_t bh0, bh1, bl0, bl1;
      ldsm2(bh0, bh1, sb + 4 * (W2H + boff));
      ldsm2(bl0, bl1, sb + 4 * (W2L + boff));
      uint32_t aoff = (uint32_t)(16 * mw + l15) * 36 + kc * 8 + lhalf * 4;
      uint32_t ah[4], al[4];
      ldsm4(ah, sb + 4 * (HNH + aoff));
      ldsm4(al, sb + 4 * (HNL + aoff));
      mma16816(acc3, ah, bh0, bh1);
      mma16816(acc3, al, bh0, bh1);
      mma16816(acc3, ah, bl0, bl1);
    }
    {
      int colb = 8 * nw + 2 * cq;
      float bq0 = smf[B2O + colb], bq1 = smf[B2O + colb + 1];
      #pragma unroll
      for (int s = 0; s < 2; ++s) {
        int row = 16 * mw + g + 8 * s;
        float q0 = acc3[2 * s] + bq0;
        float q1 = acc3[2 * s + 1] + bq1;
        *(float2*)(out_q + ((size_t)(b0 + row) * 8 + a) * 16 + colb) = make_float2(q0, q1);
      }
    }
    __syncthreads();   // hn (X region) reads done before next tile's X overwrite
  }
}

extern "C" void kernel_launch(void* const* d_in, const int* in_sizes, int n_in,
                              void* d_out, int out_size) {
  (void)n_in; (void)out_size;
  const float* inputs = (const float*)d_in[0];
  const float* hidden = (const float*)d_in[1];
  const float* W1  = (const float*)d_in[2];
  const float* b1  = (const float*)d_in[3];
  const float* Wih = (const float*)d_in[4];
  const float* bih = (const float*)d_in[5];
  const float* Whh = (const float*)d_in[6];
  const float* bhh = (const float*)d_in[7];
  const float* W2  = (const float*)d_in[8];
  const float* b2  = (const float*)d_in[9];

  const int B = in_sizes[0] / (8 * 128);   // 16384
  float* out_q = (float*)d_out;
  float* out_h = out_q + (size_t)B * 8 * 16;

  const size_t smem = (size_t)SMEM_WORDS * 4;   // 206720 B
  cudaFuncSetAttribute(rnn_persist_kernel,
                       cudaFuncAttributeMaxDynamicSharedMemorySize, (int)smem);
  dim3 grid(B / (NTILE * BB), 8, 1);            // (16, 8)
  rnn_persist_kernel<<<grid, NT, smem>>>(inputs, hidden, W1, b1, Wih, bih,
                                         Whh, bhh, W2, b2, out_q, out_h);
}

// round 6
// speedup vs baseline: 1.8960x; 1.1077x over previous
#include <cuda_runtime.h>
#include <cuda_bf16.h>
#include <cstdint>
#include <cstddef>

#define DEV __device__ __forceinline__

constexpr int NT = 512;   // 16 warps: 4 m-warps x 4 n-warps
constexpr int BB = 64;    // batch rows per tile
constexpr int TOTAL_TILES = 256;   // 16384 / 64

// ---- smem layout in 32-bit words ----
constexpr int B1O = 0, BRO = 64, BZO = 128, BINO = 192, BHNO = 256, B2O = 320;
constexpr int W1H = 352;              // [64][68] hi
constexpr int W1L = W1H + 4352;       // lo
constexpr int WIHH = W1L + 4352;      // [192][36]
constexpr int WIHL = WIHH + 6912;
constexpr int WHH_H = WIHL + 6912;
constexpr int WHH_L = WHH_H + 6912;
constexpr int W2H = WHH_L + 6912;     // [16][36]
constexpr int W2L = W2H + 576;
constexpr int XR  = W2L + 576;        // 9216-word region: X hi/lo, later z1 + hn
constexpr int XH  = XR;               // X hi [64][68]
constexpr int XL  = XR + 4352;        // X lo
constexpr int Z1H = XR;               // z1 hi [64][36] (X dead)
constexpr int Z1L = XR + 2304;
constexpr int HNH = XR + 4608;        // h_new hi [64][36]
constexpr int HNL = XR + 6912;
constexpr int HHq = XR + 9216;        // h_in hi [64][36]
constexpr int HLq = HHq + 2304;
constexpr int SMEM_WORDS = HLq + 2304;   // 51680 words = 206720 B

DEV void split2(float x, float y, uint32_t& hi, uint32_t& lo) {
  __nv_bfloat16 xh = __float2bfloat16(x), yh = __float2bfloat16(y);
  __nv_bfloat16 xl = __float2bfloat16(x - __bfloat162float(xh));
  __nv_bfloat16 yl = __float2bfloat16(y - __bfloat162float(yh));
  hi = (uint32_t)__bfloat16_as_ushort(xh) | ((uint32_t)__bfloat16_as_ushort(yh) << 16);
  lo = (uint32_t)__bfloat16_as_ushort(xl) | ((uint32_t)__bfloat16_as_ushort(yl) << 16);
}
DEV float bfbits2f(uint32_t b) { return __uint_as_float(b << 16); }
DEV float sigm(float x) { return __fdividef(1.f, 1.f + __expf(-x)); }
DEV float tanh_(float x) { float e = __expf(2.f * x); return 1.f - __fdividef(2.f, e + 1.f); }

DEV uint32_t smem_u32(const void* p) {
  uint32_t r;
  asm("{ .reg .u64 t; cvta.to.shared.u64 t, %1; cvt.u32.u64 %0, t; }" : "=r"(r) : "l"(p));
  return r;
}
DEV void mma16816(float* c, const uint32_t* a, uint32_t b0, uint32_t b1) {
  asm volatile(
      "mma.sync.aligned.m16n8k16.row.col.f32.bf16.bf16.f32 "
      "{%0,%1,%2,%3}, {%4,%5,%6,%7}, {%8,%9}, {%0,%1,%2,%3};"
      : "+f"(c[0]), "+f"(c[1]), "+f"(c[2]), "+f"(c[3])
      : "r"(a[0]), "r"(a[1]), "r"(a[2]), "r"(a[3]), "r"(b0), "r"(b1));
}
DEV void ldsm4(uint32_t* r, uint32_t addr) {
  asm volatile("ldmatrix.sync.aligned.m8n8.x4.shared.b16 {%0,%1,%2,%3}, [%4];"
               : "=r"(r[0]), "=r"(r[1]), "=r"(r[2]), "=r"(r[3]) : "r"(addr));
}
DEV void ldsm2(uint32_t& r0, uint32_t& r1, uint32_t addr) {
  asm volatile("ldmatrix.sync.aligned.m8n8.x2.shared.b16 {%0,%1}, [%2];"
               : "=r"(r0), "=r"(r1) : "r"(addr));
}

__global__ void __launch_bounds__(NT, 1)
rnn_persist16_kernel(const float* __restrict__ inputs, const float* __restrict__ hidden,
                     const float* __restrict__ W1, const float* __restrict__ b1g,
                     const float* __restrict__ Wih, const float* __restrict__ bihg,
                     const float* __restrict__ Whh, const float* __restrict__ bhhg,
                     const float* __restrict__ W2, const float* __restrict__ b2g,
                     float* __restrict__ out_q, float* __restrict__ out_h)
{
  extern __shared__ uint32_t smu[];
  float* smf = (float*)smu;
  const uint32_t sb = smem_u32(smu);
  const int a = blockIdx.y;
  const int tid = threadIdx.x;
  const int w = tid >> 5, lane = tid & 31;
  const int mw = w >> 2, nw = w & 3;          // 4 m-warps x 4 n-warps
  const int g = lane >> 2, cq = lane & 3;
  const int l15 = lane & 15, lhalf = lane >> 4;
  const int l7 = lane & 7, l8b = (lane >> 3) & 1;

  // ================= one-time: biases + weights -> bf16 hi/lo =================
  if (tid < 64) {
    smf[B1O + tid]  = b1g[a * 64 + tid];
    smf[BRO + tid]  = bihg[a * 192 + tid]       + bhhg[a * 192 + tid];
    smf[BZO + tid]  = bihg[a * 192 + 64 + tid]  + bhhg[a * 192 + 64 + tid];
    smf[BINO + tid] = bihg[a * 192 + 128 + tid];
    smf[BHNO + tid] = bhhg[a * 192 + 128 + tid];
  } else if (tid < 80) {
    smf[B2O + tid - 64] = b2g[a * 16 + tid - 64];
  }
  {
    const float* w1g = W1 + (size_t)a * 64 * 128;
    #pragma unroll 2
    for (int f = tid; f < 2048; f += NT) {            // W1 [64][128]
      int n = f >> 5, p4 = (f & 31) * 2;
      float4 v = *(const float4*)(w1g + (size_t)n * 128 + p4 * 2);
      uint32_t h0, l0, h1, l1;
      split2(v.x, v.y, h0, l0); split2(v.z, v.w, h1, l1);
      smu[W1H + n * 68 + p4] = h0; smu[W1H + n * 68 + p4 + 1] = h1;
      smu[W1L + n * 68 + p4] = l0; smu[W1L + n * 68 + p4 + 1] = l1;
    }
    const float* wig = Wih + (size_t)a * 192 * 64;
    #pragma unroll 2
    for (int f = tid; f < 3072; f += NT) {            // Wih [192][64]
      int n = f >> 4, p4 = (f & 15) * 2;
      float4 v = *(const float4*)(wig + (size_t)n * 64 + p4 * 2);
      uint32_t h0, l0, h1, l1;
      split2(v.x, v.y, h0, l0); split2(v.z, v.w, h1, l1);
      smu[WIHH + n * 36 + p4] = h0; smu[WIHH + n * 36 + p4 + 1] = h1;
      smu[WIHL + n * 36 + p4] = l0; smu[WIHL + n * 36 + p4 + 1] = l1;
    }
    const float* whg = Whh + (size_t)a * 192 * 64;
    #pragma unroll 2
    for (int f = tid; f < 3072; f += NT) {            // Whh [192][64]
      int n = f >> 4, p4 = (f & 15) * 2;
      float4 v = *(const float4*)(whg + (size_t)n * 64 + p4 * 2);
      uint32_t h0, l0, h1, l1;
      split2(v.x, v.y, h0, l0); split2(v.z, v.w, h1, l1);
      smu[WHH_H + n * 36 + p4] = h0; smu[WHH_H + n * 36 + p4 + 1] = h1;
      smu[WHH_L + n * 36 + p4] = l0; smu[WHH_L + n * 36 + p4 + 1] = l1;
    }
    const float* w2g = W2 + (size_t)a * 16 * 64;
    for (int f = tid; f < 256; f += NT) {             // W2 [16][64]
      int n = f >> 4, p4 = (f & 15) * 2;
      float4 v = *(const float4*)(w2g + (size_t)n * 64 + p4 * 2);
      uint32_t h0, l0, h1, l1;
      split2(v.x, v.y, h0, l0); split2(v.z, v.w, h1, l1);
      smu[W2H + n * 36 + p4] = h0; smu[W2H + n * 36 + p4 + 1] = h1;
      smu[W2L + n * 36 + p4] = l0; smu[W2L + n * 36 + p4 + 1] = l1;
    }
  }
  __syncthreads();

  // ================= tile loop (strided for balance over 144 CTAs) =================
  for (int t = blockIdx.x; t < TOTAL_TILES; t += gridDim.x) {
    const int b0 = t * BB;

    // ---- load + convert X, h ----
    {
      const float* xg = inputs + ((size_t)b0 * 8 + a) * 128;
      #pragma unroll 4
      for (int f = tid; f < 2048; f += NT) {          // X [64][128]
        int row = f >> 5, p4 = (f & 31) * 2;
        float4 v = *(const float4*)(xg + (size_t)row * 1024 + p4 * 2);
        uint32_t h0, l0, h1, l1;
        split2(v.x, v.y, h0, l0); split2(v.z, v.w, h1, l1);
        smu[XH + row * 68 + p4] = h0; smu[XH + row * 68 + p4 + 1] = h1;
        smu[XL + row * 68 + p4] = l0; smu[XL + row * 68 + p4 + 1] = l1;
      }
      const float* hg = hidden + ((size_t)b0 * 8 + a) * 64;
      #pragma unroll 2
      for (int f = tid; f < 1024; f += NT) {          // h [64][64]
        int row = f >> 4, p4 = (f & 15) * 2;
        float4 v = *(const float4*)(hg + (size_t)row * 512 + p4 * 2);
        uint32_t h0, l0, h1, l1;
        split2(v.x, v.y, h0, l0); split2(v.z, v.w, h1, l1);
        smu[HHq + row * 36 + p4] = h0; smu[HHq + row * 36 + p4 + 1] = h1;
        smu[HLq + row * 36 + p4] = l0; smu[HLq + row * 36 + p4 + 1] = l1;
      }
    }
    __syncthreads();

    // ---- stage 1: z1 = relu(X @ W1^T + b1); warp covers n-tiles nw, nw+4 ----
    float acc1[2][4];
    #pragma unroll
    for (int s = 0; s < 2; ++s)
      #pragma unroll
      for (int e = 0; e < 4; ++e) acc1[s][e] = 0.f;

    #pragma unroll
    for (int kc = 0; kc < 8; ++kc) {
      uint32_t ah[4], al[4];
      uint32_t aoff = (uint32_t)(16 * mw + l15) * 68 + kc * 8 + lhalf * 4;
      ldsm4(ah, sb + 4 * (XH + aoff));
      ldsm4(al, sb + 4 * (XL + aoff));
      #pragma unroll
      for (int s = 0; s < 2; ++s) {
        uint32_t boff = (uint32_t)(8 * (nw + 4 * s) + l7) * 68 + kc * 8 + l8b * 4;
        uint32_t bh0, bh1, bl0, bl1;
        ldsm2(bh0, bh1, sb + 4 * (W1H + boff));
        ldsm2(bl0, bl1, sb + 4 * (W1L + boff));
        mma16816(acc1[s], ah, bh0, bh1);
        mma16816(acc1[s], al, bh0, bh1);
        mma16816(acc1[s], ah, bl0, bl1);
      }
    }
    __syncthreads();   // X region dead

    // ---- epilogue 1: bias+relu -> z1 hi/lo ----
    #pragma unroll
    for (int s = 0; s < 2; ++s) {
      int ntile = nw + 4 * s;
      int col = 8 * ntile + 2 * cq;
      int pidx = 4 * ntile + cq;
      float bx = smf[B1O + col], by = smf[B1O + col + 1];
      #pragma unroll
      for (int sr = 0; sr < 2; ++sr) {
        int row = 16 * mw + g + 8 * sr;
        float v0 = fmaxf(acc1[s][2 * sr] + bx, 0.f);
        float v1 = fmaxf(acc1[s][2 * sr + 1] + by, 0.f);
        uint32_t ph, pl;
        split2(v0, v1, ph, pl);
        smu[Z1H + row * 36 + pidx] = ph;
        smu[Z1L + row * 36 + pidx] = pl;
      }
    }
    __syncthreads();

    // ---- stage 2: gate GEMMs. N-space 256 = [r|z|i_n|h_n]; warp owns ntile = nw + 4j ----
    float acc2[8][4];
    #pragma unroll
    for (int j = 0; j < 8; ++j)
      #pragma unroll
      for (int e = 0; e < 4; ++e) acc2[j][e] = 0.f;

    #pragma unroll
    for (int kc = 0; kc < 4; ++kc) {
      uint32_t zh[4], zl[4], hh_[4], hl_[4];
      uint32_t aoff = (uint32_t)(16 * mw + l15) * 36 + kc * 8 + lhalf * 4;
      ldsm4(zh, sb + 4 * (Z1H + aoff));
      ldsm4(zl, sb + 4 * (Z1L + aoff));
      ldsm4(hh_, sb + 4 * (HHq + aoff));
      ldsm4(hl_, sb + 4 * (HLq + aoff));
      uint32_t bbase = (uint32_t)l7 * 36 + kc * 8 + l8b * 4;
      #pragma unroll
      for (int j = 0; j < 8; ++j) {
        int ntile = nw + 4 * j;
        if (ntile < 24) {                   // z1 @ Wih rows 8*ntile  (r, z, i_n)
          uint32_t bh0, bh1, bl0, bl1;
          uint32_t o = (uint32_t)(8 * ntile) * 36 + bbase;
          ldsm2(bh0, bh1, sb + 4 * (WIHH + o));
          ldsm2(bl0, bl1, sb + 4 * (WIHL + o));
          mma16816(acc2[j], zh, bh0, bh1);
          mma16816(acc2[j], zl, bh0, bh1);
          mma16816(acc2[j], zh, bl0, bl1);
        }
        if (ntile < 16 || ntile >= 24) {    // h @ Whh (r, z rows; h_n rows-64)
          int n0 = (ntile < 16) ? 8 * ntile : 8 * ntile - 64;
          uint32_t bh0, bh1, bl0, bl1;
          uint32_t o = (uint32_t)n0 * 36 + bbase;
          ldsm2(bh0, bh1, sb + 4 * (WHH_H + o));
          ldsm2(bl0, bl1, sb + 4 * (WHH_L + o));
          mma16816(acc2[j], hh_, bh0, bh1);
          mma16816(acc2[j], hl_, bh0, bh1);
          mma16816(acc2[j], hh_, bl0, bl1);
        }
      }
    }
    __syncthreads();

    // ---- epilogue 2: GRU -> h_new (smem hi/lo + gmem) ----
    // acc2[s]=r, acc2[2+s]=z, acc2[4+s]=i_n, acc2[6+s]=h_n for columns 8*(nw+4s)
    #pragma unroll
    for (int s = 0; s < 2; ++s) {
      int ntile = nw + 4 * s;
      int cb = 8 * ntile + 2 * cq;
      int pidx = 4 * ntile + cq;
      float brv0 = smf[BRO + cb],  brv1 = smf[BRO + cb + 1];
      float bzv0 = smf[BZO + cb],  bzv1 = smf[BZO + cb + 1];
      float biv0 = smf[BINO + cb], biv1 = smf[BINO + cb + 1];
      float bnv0 = smf[BHNO + cb], bnv1 = smf[BHNO + cb + 1];
      #pragma unroll
      for (int sr = 0; sr < 2; ++sr) {
        int row = 16 * mw + g + 8 * sr;
        uint32_t uh = smu[HHq + row * 36 + pidx], ul = smu[HLq + row * 36 + pidx];
        float ho0 = bfbits2f(uh & 0xffffu) + bfbits2f(ul & 0xffffu);
        float ho1 = bfbits2f(uh >> 16) + bfbits2f(ul >> 16);
        float rv0 = sigm(acc2[s][2 * sr] + brv0);
        float rv1 = sigm(acc2[s][2 * sr + 1] + brv1);
        float zv0 = sigm(acc2[2 + s][2 * sr] + bzv0);
        float zv1 = sigm(acc2[2 + s][2 * sr + 1] + bzv1);
        float nv0 = tanh_(acc2[4 + s][2 * sr] + biv0 +
                          rv0 * (acc2[6 + s][2 * sr] + bnv0));
        float nv1 = tanh_(acc2[4 + s][2 * sr + 1] + biv1 +
                          rv1 * (acc2[6 + s][2 * sr + 1] + bnv1));
        float hn0 = nv0 + zv0 * (ho0 - nv0);
        float hn1 = nv1 + zv1 * (ho1 - nv1);
        uint32_t ph, pl;
        split2(hn0, hn1, ph, pl);
        smu[HNH + row * 36 + pidx] = ph;
        smu[HNL + row * 36 + pidx] = pl;
        *(float2*)(out_h + ((size_t)(b0 + row) * 8 + a) * 64 + cb) = make_float2(hn0, hn1);
      }
    }
    __syncthreads();

    // ---- stage 3: q = h_new @ W2^T + b2 (n-warps 0,1 only) ----
    if (nw < 2) {
      float acc3[4] = {0.f, 0.f, 0.f, 0.f};
      #pragma unroll
      for (int kc = 0; kc < 4; ++kc) {
        uint32_t boff = (uint32_t)(8 * nw + l7) * 36 + kc * 8 + l8b * 4;
        uint32_t bh0, bh1, bl0, bl1;
        ldsm2(bh0, bh1, sb + 4 * (W2H + boff));
        ldsm2(bl0, bl1, sb + 4 * (W2L + boff));
        uint32_t aoff = (uint32_t)(16 * mw + l15) * 36 + kc * 8 + lhalf * 4;
        uint32_t ah[4], al[4];
        ldsm4(ah, sb + 4 * (HNH + aoff));
        ldsm4(al, sb + 4 * (HNL + aoff));
        mma16816(acc3, ah, bh0, bh1);
        mma16816(acc3, al, bh0, bh1);
        mma16816(acc3, ah, bl0, bl1);
      }
      int colb = 8 * nw + 2 * cq;
      float bq0 = smf[B2O + colb], bq1 = smf[B2O + colb + 1];
      #pragma unroll
      for (int sr = 0; sr < 2; ++sr) {
        int row = 16 * mw + g + 8 * sr;
        float q0 = acc3[2 * sr] + bq0;
        float q1 = acc3[2 * sr + 1] + bq1;
        *(float2*)(out_q + ((size_t)(b0 + row) * 8 + a) * 16 + colb) = make_float2(q0, q1);
      }
    }
    __syncthreads();   // hn (X region) reads done before next tile's X overwrite
  }
}

extern "C" void kernel_launch(void* const* d_in, const int* in_sizes, int n_in,
                              void* d_out, int out_size) {
  (void)n_in; (void)out_size;
  const float* inputs = (const float*)d_in[0];
  const float* hidden = (const float*)d_in[1];
  const float* W1  = (const float*)d_in[2];
  const float* b1  = (const float*)d_in[3];
  const float* Wih = (const float*)d_in[4];
  const float* bih = (const float*)d_in[5];
  const float* Whh = (const float*)d_in[6];
  const float* bhh = (const float*)d_in[7];
  const float* W2  = (const float*)d_in[8];
  const float* b2  = (const float*)d_in[9];

  const int B = in_sizes[0] / (8 * 128);   // 16384
  float* out_q = (float*)d_out;
  float* out_h = out_q + (size_t)B * 8 * 16;

  const size_t smem = (size_t)SMEM_WORDS * 4;   // 206720 B
  cudaFuncSetAttribute(rnn_persist16_kernel,
                       cudaFuncAttributeMaxDynamicSharedMemorySize, (int)smem);
  dim3 grid(18, 8, 1);                          // 144 CTAs, strided tiles
  rnn_persist16_kernel<<<grid, NT, smem>>>(inputs, hidden, W1, b1, Wih, bih,
                                           Whh, bhh, W2, b2, out_q, out_h);
}

// round 7
// speedup vs baseline: 2.0830x; 1.0986x over previous
#include <cuda_runtime.h>
#include <cuda_bf16.h>
#include <cstdint>
#include <cstddef>

#define DEV __device__ __forceinline__

constexpr int NT = 512;   // 16 warps: 4 m-warps x 4 n-warps
constexpr int BB = 64;    // batch rows per tile
constexpr int TOTAL_TILES = 256;   // 16384 / 64

// ---- smem layout in 32-bit words (dedicated regions; only z1 aliases dead X) ----
constexpr int B1O = 0, BRO = 64, BZO = 128, BINO = 192, BHNO = 256, B2O = 320;
constexpr int W1H = 352;               // [64][68]
constexpr int W1L = W1H + 4352;        // 4704
constexpr int WIHH = W1L + 4352;       // 9056  [192][36]
constexpr int WIHL = WIHH + 6912;      // 15968
constexpr int WHH_H = WIHL + 6912;     // 22880
constexpr int WHH_L = WHH_H + 6912;    // 29792
constexpr int W2H = WHH_L + 6912;      // 36704 [16][36]
constexpr int W2L = W2H + 576;         // 37280
constexpr int XH  = W2L + 576;         // 37856 X hi [64][68]
constexpr int XL  = XH + 4352;         // 42208 X lo
constexpr int Z1H = XH;                // z1 hi [64][36] (aliases dead X)
constexpr int Z1L = XH + 2304;
constexpr int HNH = XL + 4352;         // 46560 h_new hi [64][36]
constexpr int HNL = HNH + 2304;        // 48864
constexpr int HHq = HNL + 2304;        // 51168 h_in hi [64][36]
constexpr int HLq = HHq + 2304;        // 53472
constexpr int SMEM_WORDS = HLq + 2304; // 55776 words = 223104 B

DEV void split2(float x, float y, uint32_t& hi, uint32_t& lo) {
  __nv_bfloat16 xh = __float2bfloat16(x), yh = __float2bfloat16(y);
  __nv_bfloat16 xl = __float2bfloat16(x - __bfloat162float(xh));
  __nv_bfloat16 yl = __float2bfloat16(y - __bfloat162float(yh));
  hi = (uint32_t)__bfloat16_as_ushort(xh) | ((uint32_t)__bfloat16_as_ushort(yh) << 16);
  lo = (uint32_t)__bfloat16_as_ushort(xl) | ((uint32_t)__bfloat16_as_ushort(yl) << 16);
}
DEV float bfbits2f(uint32_t b) { return __uint_as_float(b << 16); }
DEV float sigm(float x) { return __fdividef(1.f, 1.f + __expf(-x)); }
DEV float tanh_(float x) { float e = __expf(2.f * x); return 1.f - __fdividef(2.f, e + 1.f); }

DEV uint32_t smem_u32(const void* p) {
  uint32_t r;
  asm("{ .reg .u64 t; cvta.to.shared.u64 t, %1; cvt.u32.u64 %0, t; }" : "=r"(r) : "l"(p));
  return r;
}
DEV void mma16816(float* c, const uint32_t* a, uint32_t b0, uint32_t b1) {
  asm volatile(
      "mma.sync.aligned.m16n8k16.row.col.f32.bf16.bf16.f32 "
      "{%0,%1,%2,%3}, {%4,%5,%6,%7}, {%8,%9}, {%0,%1,%2,%3};"
      : "+f"(c[0]), "+f"(c[1]), "+f"(c[2]), "+f"(c[3])
      : "r"(a[0]), "r"(a[1]), "r"(a[2]), "r"(a[3]), "r"(b0), "r"(b1));
}
DEV void ldsm4(uint32_t* r, uint32_t addr) {
  asm volatile("ldmatrix.sync.aligned.m8n8.x4.shared.b16 {%0,%1,%2,%3}, [%4];"
               : "=r"(r[0]), "=r"(r[1]), "=r"(r[2]), "=r"(r[3]) : "r"(addr));
}
DEV void ldsm2(uint32_t& r0, uint32_t& r1, uint32_t addr) {
  asm volatile("ldmatrix.sync.aligned.m8n8.x2.shared.b16 {%0,%1}, [%2];"
               : "=r"(r0), "=r"(r1) : "r"(addr));
}

__global__ void __launch_bounds__(NT, 1)
rnn_pipe_kernel(const float* __restrict__ inputs, const float* __restrict__ hidden,
                const float* __restrict__ W1, const float* __restrict__ b1g,
                const float* __restrict__ Wih, const float* __restrict__ bihg,
                const float* __restrict__ Whh, const float* __restrict__ bhhg,
                const float* __restrict__ W2, const float* __restrict__ b2g,
                float* __restrict__ out_q, float* __restrict__ out_h)
{
  extern __shared__ uint32_t smu[];
  float* smf = (float*)smu;
  const uint32_t sb = smem_u32(smu);
  const int a = blockIdx.y;
  const int tid = threadIdx.x;
  const int w = tid >> 5, lane = tid & 31;
  const int mw = w >> 2, nw = w & 3;          // 4 m-warps x 4 n-warps
  const int g = lane >> 2, cq = lane & 3;
  const int l15 = lane & 15, lhalf = lane >> 4;
  const int l7 = lane & 7, l8b = (lane >> 3) & 1;

  // ================= one-time: biases + weights -> bf16 hi/lo =================
  if (tid < 64) {
    smf[B1O + tid]  = b1g[a * 64 + tid];
    smf[BRO + tid]  = bihg[a * 192 + tid]       + bhhg[a * 192 + tid];
    smf[BZO + tid]  = bihg[a * 192 + 64 + tid]  + bhhg[a * 192 + 64 + tid];
    smf[BINO + tid] = bihg[a * 192 + 128 + tid];
    smf[BHNO + tid] = bhhg[a * 192 + 128 + tid];
  } else if (tid < 80) {
    smf[B2O + tid - 64] = b2g[a * 16 + tid - 64];
  }
  {
    const float* w1g = W1 + (size_t)a * 64 * 128;
    #pragma unroll 2
    for (int f = tid; f < 2048; f += NT) {            // W1 [64][128]
      int n = f >> 5, p4 = (f & 31) * 2;
      float4 v = *(const float4*)(w1g + (size_t)n * 128 + p4 * 2);
      uint32_t h0, l0, h1, l1;
      split2(v.x, v.y, h0, l0); split2(v.z, v.w, h1, l1);
      smu[W1H + n * 68 + p4] = h0; smu[W1H + n * 68 + p4 + 1] = h1;
      smu[W1L + n * 68 + p4] = l0; smu[W1L + n * 68 + p4 + 1] = l1;
    }
    const float* wig = Wih + (size_t)a * 192 * 64;
    #pragma unroll 2
    for (int f = tid; f < 3072; f += NT) {            // Wih [192][64]
      int n = f >> 4, p4 = (f & 15) * 2;
      float4 v = *(const float4*)(wig + (size_t)n * 64 + p4 * 2);
      uint32_t h0, l0, h1, l1;
      split2(v.x, v.y, h0, l0); split2(v.z, v.w, h1, l1);
      smu[WIHH + n * 36 + p4] = h0; smu[WIHH + n * 36 + p4 + 1] = h1;
      smu[WIHL + n * 36 + p4] = l0; smu[WIHL + n * 36 + p4 + 1] = l1;
    }
    const float* whg = Whh + (size_t)a * 192 * 64;
    #pragma unroll 2
    for (int f = tid; f < 3072; f += NT) {            // Whh [192][64]
      int n = f >> 4, p4 = (f & 15) * 2;
      float4 v = *(const float4*)(whg + (size_t)n * 64 + p4 * 2);
      uint32_t h0, l0, h1, l1;
      split2(v.x, v.y, h0, l0); split2(v.z, v.w, h1, l1);
      smu[WHH_H + n * 36 + p4] = h0; smu[WHH_H + n * 36 + p4 + 1] = h1;
      smu[WHH_L + n * 36 + p4] = l0; smu[WHH_L + n * 36 + p4 + 1] = l1;
    }
    const float* w2g = W2 + (size_t)a * 16 * 64;
    for (int f = tid; f < 256; f += NT) {             // W2 [16][64]
      int n = f >> 4, p4 = (f & 15) * 2;
      float4 v = *(const float4*)(w2g + (size_t)n * 64 + p4 * 2);
      uint32_t h0, l0, h1, l1;
      split2(v.x, v.y, h0, l0); split2(v.z, v.w, h1, l1);
      smu[W2H + n * 36 + p4] = h0; smu[W2H + n * 36 + p4 + 1] = h1;
      smu[W2L + n * 36 + p4] = l0; smu[W2L + n * 36 + p4 + 1] = l1;
    }
  }

  // ================= prologue: load first tile's X, h =================
  {
    const int b0 = blockIdx.x * BB;
    const float* xg = inputs + ((size_t)b0 * 8 + a) * 128;
    #pragma unroll 4
    for (int f = tid; f < 2048; f += NT) {            // X [64][128]
      int row = f >> 5, p4 = (f & 31) * 2;
      float4 v = *(const float4*)(xg + (size_t)row * 1024 + p4 * 2);
      uint32_t h0, l0, h1, l1;
      split2(v.x, v.y, h0, l0); split2(v.z, v.w, h1, l1);
      smu[XH + row * 68 + p4] = h0; smu[XH + row * 68 + p4 + 1] = h1;
      smu[XL + row * 68 + p4] = l0; smu[XL + row * 68 + p4 + 1] = l1;
    }
    const float* hg = hidden + ((size_t)b0 * 8 + a) * 64;
    #pragma unroll 2
    for (int f = tid; f < 1024; f += NT) {            // h [64][64]
      int row = f >> 4, p4 = (f & 15) * 2;
      float4 v = *(const float4*)(hg + (size_t)row * 512 + p4 * 2);
      uint32_t h0, l0, h1, l1;
      split2(v.x, v.y, h0, l0); split2(v.z, v.w, h1, l1);
      smu[HHq + row * 36 + p4] = h0; smu[HHq + row * 36 + p4 + 1] = h1;
      smu[HLq + row * 36 + p4] = l0; smu[HLq + row * 36 + p4 + 1] = l1;
    }
  }
  __syncthreads();

  // ================= pipelined tile loop =================
  const int G = gridDim.x;
  const int hli = (mw * 2 + (nw - 2)) * 32 + lane;    // h-prefetch linear id (nw>=2)

  for (int t = blockIdx.x; t < TOTAL_TILES; t += G) {
    const int b0 = t * BB;
    const int tn = t + G;
    const bool have_next = tn < TOTAL_TILES;
    const int bn = tn * BB;

    // ---- stage 1: z1 = relu(X @ W1^T + b1); warp covers n-tiles nw, nw+4 ----
    float acc1[2][4];
    #pragma unroll
    for (int s = 0; s < 2; ++s)
      #pragma unroll
      for (int e = 0; e < 4; ++e) acc1[s][e] = 0.f;

    #pragma unroll
    for (int kc = 0; kc < 8; ++kc) {
      uint32_t ah[4], al[4];
      uint32_t aoff = (uint32_t)(16 * mw + l15) * 68 + kc * 8 + lhalf * 4;
      ldsm4(ah, sb + 4 * (XH + aoff));
      ldsm4(al, sb + 4 * (XL + aoff));
      #pragma unroll
      for (int s = 0; s < 2; ++s) {
        uint32_t boff = (uint32_t)(8 * (nw + 4 * s) + l7) * 68 + kc * 8 + l8b * 4;
        uint32_t bh0, bh1, bl0, bl1;
        ldsm2(bh0, bh1, sb + 4 * (W1H + boff));
        ldsm2(bl0, bl1, sb + 4 * (W1L + boff));
        mma16816(acc1[s], ah, bh0, bh1);
        mma16816(acc1[s], al, bh0, bh1);
        mma16816(acc1[s], ah, bl0, bl1);
      }
    }
    __syncthreads();   // A: all X reads done (z1 may overwrite X region)

    // ---- epilogue 1: bias+relu -> z1 hi/lo (aliases dead X) ----
    #pragma unroll
    for (int s = 0; s < 2; ++s) {
      int ntile = nw + 4 * s;
      int col = 8 * ntile + 2 * cq;
      int pidx = 4 * ntile + cq;
      float bx = smf[B1O + col], by = smf[B1O + col + 1];
      #pragma unroll
      for (int sr = 0; sr < 2; ++sr) {
        int row = 16 * mw + g + 8 * sr;
        float v0 = fmaxf(acc1[s][2 * sr] + bx, 0.f);
        float v1 = fmaxf(acc1[s][2 * sr + 1] + by, 0.f);
        uint32_t ph, pl;
        split2(v0, v1, ph, pl);
        smu[Z1H + row * 36 + pidx] = ph;
        smu[Z1L + row * 36 + pidx] = pl;
      }
    }

    // ---- prefetch next tile's X (all threads) and h (nw>=2 threads) ----
    float4 pfx[4], pfh[4];
    if (have_next) {
      const float* xg = inputs + ((size_t)bn * 8 + a) * 128;
      #pragma unroll
      for (int k = 0; k < 4; ++k) {
        int f = tid + k * NT;
        int row = f >> 5, p4 = (f & 31) * 2;
        pfx[k] = *(const float4*)(xg + (size_t)row * 1024 + p4 * 2);
      }
      if (nw >= 2) {
        const float* hg = hidden + ((size_t)bn * 8 + a) * 64;
        #pragma unroll
        for (int k = 0; k < 4; ++k) {
          int f = hli + k * 256;
          int row = f >> 4, p4 = (f & 15) * 2;
          pfh[k] = *(const float4*)(hg + (size_t)row * 512 + p4 * 2);
        }
      }
    }
    __syncthreads();   // B: z1 visible

    // ---- stage 2: gate GEMMs. N-space 256 = [r|z|i_n|h_n]; warp owns ntile = nw + 4j ----
    float acc2[8][4];
    #pragma unroll
    for (int j = 0; j < 8; ++j)
      #pragma unroll
      for (int e = 0; e < 4; ++e) acc2[j][e] = 0.f;

    #pragma unroll
    for (int kc = 0; kc < 4; ++kc) {
      uint32_t zh[4], zl[4], hh_[4], hl_[4];
      uint32_t aoff = (uint32_t)(16 * mw + l15) * 36 + kc * 8 + lhalf * 4;
      ldsm4(zh, sb + 4 * (Z1H + aoff));
      ldsm4(zl, sb + 4 * (Z1L + aoff));
      ldsm4(hh_, sb + 4 * (HHq + aoff));
      ldsm4(hl_, sb + 4 * (HLq + aoff));
      uint32_t bbase = (uint32_t)l7 * 36 + kc * 8 + l8b * 4;
      #pragma unroll
      for (int j = 0; j < 8; ++j) {
        int ntile = nw + 4 * j;
        if (ntile < 24) {                   // z1 @ Wih rows 8*ntile  (r, z, i_n)
          uint32_t bh0, bh1, bl0, bl1;
          uint32_t o = (uint32_t)(8 * ntile) * 36 + bbase;
          ldsm2(bh0, bh1, sb + 4 * (WIHH + o));
          ldsm2(bl0, bl1, sb + 4 * (WIHL + o));
          mma16816(acc2[j], zh, bh0, bh1);
          mma16816(acc2[j], zl, bh0, bh1);
          mma16816(acc2[j], zh, bl0, bl1);
        }
        if (ntile < 16 || ntile >= 24) {    // h @ Whh (r, z rows; h_n rows-64)
          int n0 = (ntile < 16) ? 8 * ntile : 8 * ntile - 64;
          uint32_t bh0, bh1, bl0, bl1;
          uint32_t o = (uint32_t)n0 * 36 + bbase;
          ldsm2(bh0, bh1, sb + 4 * (WHH_H + o));
          ldsm2(bl0, bl1, sb + 4 * (WHH_L + o));
          mma16816(acc2[j], hh_, bh0, bh1);
          mma16816(acc2[j], hl_, bh0, bh1);
          mma16816(acc2[j], hh_, bl0, bl1);
        }
      }
    }
    __syncthreads();   // C: z1 / h reads done

    // ---- epilogue 2: GRU -> h_new (+gmem); store next X (X region dead) ----
    #pragma unroll
    for (int s = 0; s < 2; ++s) {
      int ntile = nw + 4 * s;
      int cb = 8 * ntile + 2 * cq;
      int pidx = 4 * ntile + cq;
      float brv0 = smf[BRO + cb],  brv1 = smf[BRO + cb + 1];
      float bzv0 = smf[BZO + cb],  bzv1 = smf[BZO + cb + 1];
      float biv0 = smf[BINO + cb], biv1 = smf[BINO + cb + 1];
      float bnv0 = smf[BHNO + cb], bnv1 = smf[BHNO + cb + 1];
      #pragma unroll
      for (int sr = 0; sr < 2; ++sr) {
        int row = 16 * mw + g + 8 * sr;
        uint32_t uh = smu[HHq + row * 36 + pidx], ul = smu[HLq + row * 36 + pidx];
        float ho0 = bfbits2f(uh & 0xffffu) + bfbits2f(ul & 0xffffu);
        float ho1 = bfbits2f(uh >> 16) + bfbits2f(ul >> 16);
        float rv0 = sigm(acc2[s][2 * sr] + brv0);
        float rv1 = sigm(acc2[s][2 * sr + 1] + brv1);
        float zv0 = sigm(acc2[2 + s][2 * sr] + bzv0);
        float zv1 = sigm(acc2[2 + s][2 * sr + 1] + bzv1);
        float nv0 = tanh_(acc2[4 + s][2 * sr] + biv0 +
                          rv0 * (acc2[6 + s][2 * sr] + bnv0));
        float nv1 = tanh_(acc2[4 + s][2 * sr + 1] + biv1 +
                          rv1 * (acc2[6 + s][2 * sr + 1] + bnv1));
        float hn0 = nv0 + zv0 * (ho0 - nv0);
        float hn1 = nv1 + zv1 * (ho1 - nv1);
        uint32_t ph, pl;
        split2(hn0, hn1, ph, pl);
        smu[HNH + row * 36 + pidx] = ph;
        smu[HNL + row * 36 + pidx] = pl;
        *(float2*)(out_h + ((size_t)(b0 + row) * 8 + a) * 64 + cb) = make_float2(hn0, hn1);
      }
    }
    if (have_next) {
      #pragma unroll
      for (int k = 0; k < 4; ++k) {
        int f = tid + k * NT;
        int row = f >> 5, p4 = (f & 31) * 2;
        uint32_t h0, l0, h1, l1;
        split2(pfx[k].x, pfx[k].y, h0, l0); split2(pfx[k].z, pfx[k].w, h1, l1);
        smu[XH + row * 68 + p4] = h0; smu[XH + row * 68 + p4 + 1] = h1;
        smu[XL + row * 68 + p4] = l0; smu[XL + row * 68 + p4 + 1] = l1;
      }
    }
    __syncthreads();   // D: hn + next-X visible

    // ---- stage 3 (n-warps 0,1) in parallel with next-h store (n-warps 2,3) ----
    if (nw < 2) {
      float acc3[4] = {0.f, 0.f, 0.f, 0.f};
      #pragma unroll
      for (int kc = 0; kc < 4; ++kc) {
        uint32_t boff = (uint32_t)(8 * nw + l7) * 36 + kc * 8 + l8b * 4;
        uint32_t bh0, bh1, bl0, bl1;
        ldsm2(bh0, bh1, sb + 4 * (W2H + boff));
        ldsm2(bl0, bl1, sb + 4 * (W2L + boff));
        uint32_t aoff = (uint32_t)(16 * mw + l15) * 36 + kc * 8 + lhalf * 4;
        uint32_t ah[4], al[4];
        ldsm4(ah, sb + 4 * (HNH + aoff));
        ldsm4(al, sb + 4 * (HNL + aoff));
        mma16816(acc3, ah, bh0, bh1);
        mma16816(acc3, al, bh0, bh1);
        mma16816(acc3, ah, bl0, bl1);
      }
      int colb = 8 * nw + 2 * cq;
      float bq0 = smf[B2O + colb], bq1 = smf[B2O + colb + 1];
      #pragma unroll
      for (int sr = 0; sr < 2; ++sr) {
        int row = 16 * mw + g + 8 * sr;
        float q0 = acc3[2 * sr] + bq0;
        float q1 = acc3[2 * sr + 1] + bq1;
        *(float2*)(out_q + ((size_t)(b0 + row) * 8 + a) * 16 + colb) = make_float2(q0, q1);
      }
    } else if (have_next) {
      #pragma unroll
      for (int k = 0; k < 4; ++k) {
        int f = hli + k * 256;
        int row = f >> 4, p4 = (f & 15) * 2;
        uint32_t h0, l0, h1, l1;
        split2(pfh[k].x, pfh[k].y, h0, l0); split2(pfh[k].z, pfh[k].w, h1, l1);
        smu[HHq + row * 36 + p4] = h0; smu[HHq + row * 36 + p4 + 1] = h1;
        smu[HLq + row * 36 + p4] = l0; smu[HLq + row * 36 + p4 + 1] = l1;
      }
    }
    // no sync needed here: stage1(t+1) touches only X/W1; next write to hn/h
    // regions happens after syncs A and C of the next iteration.
  }
}

extern "C" void kernel_launch(void* const* d_in, const int* in_sizes, int n_in,
                              void* d_out, int out_size) {
  (void)n_in; (void)out_size;
  const float* inputs = (const float*)d_in[0];
  const float* hidden = (const float*)d_in[1];
  const float* W1  = (const float*)d_in[2];
  const float* b1  = (const float*)d_in[3];
  const float* Wih = (const float*)d_in[4];
  const float* bih = (const float*)d_in[5];
  const float* Whh = (const float*)d_in[6];
  const float* bhh = (const float*)d_in[7];
  const float* W2  = (const float*)d_in[8];
  const float* b2  = (const float*)d_in[9];

  const int B = in_sizes[0] / (8 * 128);   // 16384
  float* out_q = (float*)d_out;
  float* out_h = out_q + (size_t)B * 8 * 16;

  const size_t smem = (size_t)SMEM_WORDS * 4;   // 223104 B
  cudaFuncSetAttribute(rnn_pipe_kernel,
                       cudaFuncAttributeMaxDynamicSharedMemorySize, (int)smem);
  dim3 grid(18, 8, 1);                          // 144 CTAs, strided tiles
  rnn_pipe_kernel<<<grid, NT, smem>>>(inputs, hidden, W1, b1, Wih, bih,
                                      Whh, bhh, W2, b2, out_q, out_h);
}